// round 5
// baseline (speedup 1.0000x reference)
#include <cuda_runtime.h>

// ---------------------------------------------------------------------------
// Problem constants
// ---------------------------------------------------------------------------
#define TT   512
#define BB   1024
#define IN1  80
#define NH1  100
#define NG1  400
#define NH2  50
#define NG2  200

typedef unsigned long long ull;

// ---------------------------------------------------------------------------
// Device scratch
// ---------------------------------------------------------------------------
__device__ __align__(16) float g_pre1[(size_t)BB * TT * NG1];   // [b][t][400]
__device__ __align__(16) float g_h1  [(size_t)BB * TT * NH1];   // [b][t][100]
__device__ __align__(16) float g_pre2[(size_t)BB * TT * NG2];   // [b][t][200]

// GEMM weights: [k][pair][2] floats, pairs padded (208 / 104), zero-filled
__device__ __align__(16) float g_w1p[IN1 * 208 * 2];
__device__ __align__(16) float g_w2p[NH1 * 104 * 2];
// LSTM recurrent weights: plain [k][g]
__device__ __align__(16) float g_whh1T[NH1 * NG1];
__device__ __align__(16) float g_whh2T[NH2 * NG2];
// Fused biases, zero-padded
__device__ __align__(16) float g_b1[512];
__device__ __align__(16) float g_b2[512];

// ---------------------------------------------------------------------------
// f32x2 helpers (FFMA2 via PTX fma.rn.f32x2; bit-exact vs scalar FFMA)
// ---------------------------------------------------------------------------
__device__ __forceinline__ ull ffma2(ull d, ull a, ull b) {
    asm("fma.rn.f32x2 %0, %1, %2, %0;" : "+l"(d) : "l"(a), "l"(b));
    return d;
}
__device__ __forceinline__ ull dup2(float x) {
    ull r; unsigned u = __float_as_uint(x);
    asm("mov.b64 %0, {%1, %1};" : "=l"(r) : "r"(u));
    return r;
}
__device__ __forceinline__ ull pk(float x, float y) {
    ull r;
    asm("mov.b64 %0, {%1, %2};" : "=l"(r) : "f"(x), "f"(y));
    return r;
}
__device__ __forceinline__ void upk(ull v, float& a, float& b) {
    unsigned lo, hi;
    asm("mov.b64 {%0, %1}, %2;" : "=r"(lo), "=r"(hi) : "l"(v));
    a = __uint_as_float(lo); b = __uint_as_float(hi);
}

// Accurate fast activations (~1e-6 rel; NOT tanh.approx)
__device__ __forceinline__ float sigm(float x) {
    return __fdividef(1.0f, 1.0f + __expf(-x));
}
__device__ __forceinline__ float tanh_f(float x) {
    return __fdividef(2.0f, 1.0f + __expf(-2.0f * x)) - 1.0f;
}

// ---------------------------------------------------------------------------
// prep
// ---------------------------------------------------------------------------
__global__ void prep_kernel(const float* __restrict__ Wih1, const float* __restrict__ Whh1,
                            const float* __restrict__ bih1, const float* __restrict__ bhh1,
                            const float* __restrict__ Wih2, const float* __restrict__ Whh2,
                            const float* __restrict__ bih2, const float* __restrict__ bhh2) {
    int tid = blockIdx.x * blockDim.x + threadIdx.x;
    int stride = gridDim.x * blockDim.x;

    for (int i = tid; i < IN1 * 208 * 2; i += stride) {
        int k = i / (208 * 2), g = i % (208 * 2);
        g_w1p[i] = (g < NG1) ? Wih1[g * IN1 + k] : 0.0f;
    }
    for (int i = tid; i < NH1 * 104 * 2; i += stride) {
        int k = i / (104 * 2), g = i % (104 * 2);
        g_w2p[i] = (g < NG2) ? Wih2[g * NH1 + k] : 0.0f;
    }
    for (int i = tid; i < NH1 * NG1; i += stride) { int k = i / NG1, g = i % NG1; g_whh1T[i] = Whh1[g * NH1 + k]; }
    for (int i = tid; i < NH2 * NG2; i += stride) { int k = i / NG2, g = i % NG2; g_whh2T[i] = Whh2[g * NH2 + k]; }
    for (int i = tid; i < 512; i += stride) {
        g_b1[i] = (i < NG1) ? bih1[i] + bhh1[i] : 0.0f;
        g_b2[i] = (i < NG2) ? bih2[i] + bhh2[i] : 0.0f;
    }
}

// ---------------------------------------------------------------------------
// GEMM: out[m][GR] = x[m][K] @ W + b.  M=64 tile, 13 warps, 2 CTAs/SM.
// blockIdx.y selects a 104-pair column panel (gemm1 has 2, gemm2 has 1).
// Lane owns rows 2l,2l+1 (coalesced LDS.64 x); warp owns 8 pairs (4 broadcast
// LDS.128 w). Per warp per k: 6 wf + 16 FFMA2 + 2 mov -> FFMA2-pipe bound.
// ---------------------------------------------------------------------------
template<int K, int GR, int PADTOT>
__global__ __launch_bounds__(416, 2)
void gemm_kernel(const float* __restrict__ x, const float* __restrict__ wp,
                 const float* __restrict__ bias, float* __restrict__ out) {
    constexpr int PADP = 104;               // pairs per panel
    constexpr int XP   = 68;                // padded row-dim for x tile
    extern __shared__ float sm[];
    ull*   swp = (ull*)sm;                  // [k][PADP] pairs
    float* sx  = sm + K * PADP * 2;         // [k][XP] transposed x tile

    int tid  = threadIdx.x;
    int lane = tid & 31;
    int wi   = tid >> 5;
    int m0   = blockIdx.x * 64;
    int pb   = blockIdx.y * PADP;           // pair base in global pair space

    const ull* wpu = (const ull*)wp;
    for (int i = tid; i < K * PADP; i += 416) {
        int k = i / PADP, p = i - k * PADP;
        swp[i] = wpu[(size_t)k * (PADTOT / 2) + pb + p];
    }
    for (int i = tid; i < 64 * K; i += 416) {
        int r = i / K, k = i - r * K;
        sx[k * XP + r] = x[(size_t)(m0 + r) * K + k];
    }
    __syncthreads();

    int p0 = wi * 8;                        // warp's first pair within panel

    ull acc[2][8];
#pragma unroll
    for (int j = 0; j < 8; j++) {
        ull b = pk(bias[2 * (pb + p0 + j)], bias[2 * (pb + p0 + j) + 1]);
        acc[0][j] = b; acc[1][j] = b;
    }

#pragma unroll 2
    for (int k = 0; k < K; k++) {
        float2 xv = *(const float2*)(sx + k * XP + 2 * lane);
        ull xd0 = dup2(xv.x), xd1 = dup2(xv.y);
        const ull* wr = swp + k * PADP + p0;
        ulonglong2 w01 = *(const ulonglong2*)(wr + 0);
        ulonglong2 w23 = *(const ulonglong2*)(wr + 2);
        ulonglong2 w45 = *(const ulonglong2*)(wr + 4);
        ulonglong2 w67 = *(const ulonglong2*)(wr + 6);
        acc[0][0] = ffma2(acc[0][0], xd0, w01.x); acc[1][0] = ffma2(acc[1][0], xd1, w01.x);
        acc[0][1] = ffma2(acc[0][1], xd0, w01.y); acc[1][1] = ffma2(acc[1][1], xd1, w01.y);
        acc[0][2] = ffma2(acc[0][2], xd0, w23.x); acc[1][2] = ffma2(acc[1][2], xd1, w23.x);
        acc[0][3] = ffma2(acc[0][3], xd0, w23.y); acc[1][3] = ffma2(acc[1][3], xd1, w23.y);
        acc[0][4] = ffma2(acc[0][4], xd0, w45.x); acc[1][4] = ffma2(acc[1][4], xd1, w45.x);
        acc[0][5] = ffma2(acc[0][5], xd0, w45.y); acc[1][5] = ffma2(acc[1][5], xd1, w45.y);
        acc[0][6] = ffma2(acc[0][6], xd0, w67.x); acc[1][6] = ffma2(acc[1][6], xd1, w67.x);
        acc[0][7] = ffma2(acc[0][7], xd0, w67.y); acc[1][7] = ffma2(acc[1][7], xd1, w67.y);
    }

#pragma unroll
    for (int r = 0; r < 2; r++) {
        size_t m = (size_t)(m0 + 2 * lane + r);
#pragma unroll
        for (int j = 0; j < 8; j++) {
            int pp = pb + p0 + j;
            if (2 * pp < GR)
                *(ull*)(out + m * GR + 2 * pp) = acc[r][j];
        }
    }
}

// ---------------------------------------------------------------------------
// Persistent LSTM: 8 batch rows/CTA, 128 CTAs, k-split 2.
// Gate phase: NACT = 2*(G/2) threads; thread = (ks, cg) covers all 8 rows x
//   2 cols over half the k range. Per k: 2 broadcast LDS.128 (h, [k][12]) +
//   1 coalesced LDS.64 (w) + 2 dup + 8 FFMA2.
// Update phase: sums the 2 k-partials from sgt ([g][13], conflict-free reads).
// ---------------------------------------------------------------------------
template<int H, bool LAST_ONLY>
__global__ __launch_bounds__(416, 1)
void lstm_kernel(const float* __restrict__ pre, const float* __restrict__ whhT,
                 float* __restrict__ hout) {
    constexpr int G    = 4 * H;
    constexpr int NCOL = G / 2;        // gate threads per k-half (200 / 100)
    constexpr int NACT = 2 * NCOL;     // total gate threads (400 / 200)
    constexpr int KH   = H / 2;        // k per split (50 / 25)
    constexpr int RPS  = 13;           // sgt row pad (conflict-free update reads)
    constexpr int RPH  = 12;           // shp row pad (16B-aligned LDS.128)

    extern __shared__ float sm[];
    float* sw   = sm;                          // [H][G] weights
    float* sgt0 = sm + H * G;                  // [G][13] partial ks=0
    float* sgt1 = sgt0 + G * RPS;              // [G][13] partial ks=1
    float* shp  = sgt1 + G * RPS;              // [H][12] h rows 0..7

    int tid = threadIdx.x;
    int b0  = blockIdx.x * 8;

    for (int i = tid; i < H * G; i += blockDim.x) sw[i] = whhT[i];
    for (int i = tid; i < H * RPH; i += blockDim.x) shp[i] = 0.0f;
    __syncthreads();

    bool gate = (tid < NACT);
    int ks = 0, cg = 0;
    if (gate) { ks = tid / NCOL; cg = tid - ks * NCOL; }
    int c0 = 2 * cg;
    int k0 = ks * KH;
    float* sgtp = ks ? sgt1 : sgt0;

    // update mapping: unit u = tid + i*NACT -> j = tid % H (lane-fast), r = u/H
    int uj = tid % H;
    int ur[2];
    ur[0] = tid / H;
    ur[1] = tid / H + NACT / H;
    float cst[2] = {0.0f, 0.0f};

    float pv[8][2];
    if (gate && ks == 0) {
#pragma unroll
        for (int r = 0; r < 8; r++) {
            float2 v = *(const float2*)(pre + ((size_t)(b0 + r) * TT) * G + c0);
            pv[r][0] = v.x; pv[r][1] = v.y;
        }
    }

    for (int t = 0; t < TT; t++) {
        if (gate) {
            ull acc[4][2];
            if (ks == 0) {
#pragma unroll
                for (int q = 0; q < 4; q++) {
                    acc[q][0] = pk(pv[2 * q][0], pv[2 * q + 1][0]);
                    acc[q][1] = pk(pv[2 * q][1], pv[2 * q + 1][1]);
                }
                int tn = (t + 1 < TT) ? t + 1 : t;
#pragma unroll
                for (int r = 0; r < 8; r++) {
                    float2 v = *(const float2*)(pre + ((size_t)(b0 + r) * TT + tn) * G + c0);
                    pv[r][0] = v.x; pv[r][1] = v.y;
                }
            } else {
#pragma unroll
                for (int q = 0; q < 4; q++) { acc[q][0] = 0ULL; acc[q][1] = 0ULL; }
            }

#pragma unroll 2
            for (int k = k0; k < k0 + KH; k++) {
                ulonglong2 hA = *(const ulonglong2*)(shp + k * RPH);       // rows 0-3
                ulonglong2 hB = *(const ulonglong2*)(shp + k * RPH + 4);   // rows 4-7
                float2 w = *(const float2*)(sw + k * G + c0);
                ull w0 = dup2(w.x), w1 = dup2(w.y);
                acc[0][0] = ffma2(acc[0][0], hA.x, w0); acc[0][1] = ffma2(acc[0][1], hA.x, w1);
                acc[1][0] = ffma2(acc[1][0], hA.y, w0); acc[1][1] = ffma2(acc[1][1], hA.y, w1);
                acc[2][0] = ffma2(acc[2][0], hB.x, w0); acc[2][1] = ffma2(acc[2][1], hB.x, w1);
                acc[3][0] = ffma2(acc[3][0], hB.y, w0); acc[3][1] = ffma2(acc[3][1], hB.y, w1);
            }
#pragma unroll
            for (int j = 0; j < 2; j++) {
                float* col = sgtp + (c0 + j) * RPS;
#pragma unroll
                for (int q = 0; q < 4; q++) {
                    float f0, f1; upk(acc[q][j], f0, f1);
                    col[2 * q]     = f0;
                    col[2 * q + 1] = f1;
                }
            }
        }
        __syncthreads();

        if (tid < NACT) {
#pragma unroll
            for (int i = 0; i < 2; i++) {
                int r = ur[i], j = uj;
                float gi = sgt0[(0 * H + j) * RPS + r] + sgt1[(0 * H + j) * RPS + r];
                float gf = sgt0[(1 * H + j) * RPS + r] + sgt1[(1 * H + j) * RPS + r];
                float gg = sgt0[(2 * H + j) * RPS + r] + sgt1[(2 * H + j) * RPS + r];
                float go = sgt0[(3 * H + j) * RPS + r] + sgt1[(3 * H + j) * RPS + r];
                float ig = sigm(gi);
                float fg = sigm(gf);
                float gv = tanh_f(gg);
                float og = sigm(go);
                float c  = fg * cst[i] + ig * gv;
                cst[i] = c;
                float h  = og * tanh_f(c);
                shp[j * RPH + r] = h;
                if (!LAST_ONLY) {
                    hout[((size_t)(b0 + r) * TT + t) * H + j] = h;
                } else if (t == TT - 1) {
                    hout[(size_t)(b0 + r) * H + j] = h;
                }
            }
        }
        __syncthreads();
    }
}

// ---------------------------------------------------------------------------
// Launch
// ---------------------------------------------------------------------------
extern "C" void kernel_launch(void* const* d_in, const int* in_sizes, int n_in,
                              void* d_out, int out_size) {
    const float* x    = (const float*)d_in[0];
    const float* Wih1 = (const float*)d_in[1];
    const float* Whh1 = (const float*)d_in[2];
    const float* bih1 = (const float*)d_in[3];
    const float* bhh1 = (const float*)d_in[4];
    const float* Wih2 = (const float*)d_in[5];
    const float* Whh2 = (const float*)d_in[6];
    const float* bih2 = (const float*)d_in[7];
    const float* bhh2 = (const float*)d_in[8];
    float* out = (float*)d_out;
    (void)in_sizes; (void)n_in; (void)out_size;

    void *pre1, *h1, *pre2, *w1p, *w2p, *whh1T, *whh2T, *b1, *b2;
    cudaGetSymbolAddress(&pre1,  g_pre1);
    cudaGetSymbolAddress(&h1,    g_h1);
    cudaGetSymbolAddress(&pre2,  g_pre2);
    cudaGetSymbolAddress(&w1p,   g_w1p);
    cudaGetSymbolAddress(&w2p,   g_w2p);
    cudaGetSymbolAddress(&whh1T, g_whh1T);
    cudaGetSymbolAddress(&whh2T, g_whh2T);
    cudaGetSymbolAddress(&b1,    g_b1);
    cudaGetSymbolAddress(&b2,    g_b2);

    const int SMEM_G1 = IN1 * 104 * 8 + IN1 * 68 * 4;                   //  88320
    const int SMEM_G2 = NH1 * 104 * 8 + NH1 * 68 * 4;                   // 110400
    const int SMEM_L1 = NH1 * NG1 * 4 + 2 * NG1 * 13 * 4 + NH1 * 12 * 4; // 206400
    const int SMEM_L2 = NH2 * NG2 * 4 + 2 * NG2 * 13 * 4 + NH2 * 12 * 4; //  63200

    cudaFuncSetAttribute(gemm_kernel<IN1, NG1, 416>, cudaFuncAttributeMaxDynamicSharedMemorySize, SMEM_G1);
    cudaFuncSetAttribute(gemm_kernel<NH1, NG2, 208>, cudaFuncAttributeMaxDynamicSharedMemorySize, SMEM_G2);
    cudaFuncSetAttribute(lstm_kernel<NH1, false>, cudaFuncAttributeMaxDynamicSharedMemorySize, SMEM_L1);
    cudaFuncSetAttribute(lstm_kernel<NH2, true>,  cudaFuncAttributeMaxDynamicSharedMemorySize, SMEM_L2);

    prep_kernel<<<96, 256>>>(Wih1, Whh1, bih1, bhh1, Wih2, Whh2, bih2, bhh2);

    gemm_kernel<IN1, NG1, 416><<<dim3(BB * TT / 64, 2), 416, SMEM_G1>>>(
        x, (const float*)w1p, (const float*)b1, (float*)pre1);

    lstm_kernel<NH1, false><<<BB / 8, 416, SMEM_L1>>>(
        (const float*)pre1, (const float*)whh1T, (float*)h1);

    gemm_kernel<NH1, NG2, 208><<<dim3(BB * TT / 64, 1), 416, SMEM_G2>>>(
        (const float*)h1, (const float*)w2p, (const float*)b2, (float*)pre2);

    lstm_kernel<NH2, true><<<BB / 8, 224, SMEM_L2>>>(
        (const float*)pre2, (const float*)whh2T, out);
}